// round 10
// baseline (speedup 1.0000x reference)
#include <cuda_runtime.h>
#include <cuda_bf16.h>
#include <math.h>

// Problem constants
#define BB   4
#define SS   4096
#define HH   2048
#define VV   32000
#define IDIM 64
#define NLC  8192
#define NPOS (BB * SS)          // 16384 output rows
#define H4   (HH / 4)           // 512 float4 per row

#define GEMM_BLOCKS 2048                  // 16 col-tiles x 128 row-tiles
#define COPY_BLOCKS (NPOS * H4 / 256)     // 32768

typedef unsigned long long ull;

// Device scratch (no allocations allowed)
__device__ float d_g2[NLC * IDIM];   // gelu(h2) per lc row, 2 MB
__device__ int   d_owner[NPOS];      // winning lc index per position, -1 if none
__device__ int   d_cpos[NLC];        // compacted flat positions
__device__ int   d_cj[NLC];          // compacted lc indices
__device__ int   d_cnt;              // number of unique owned positions

__device__ __forceinline__ float gelu_exact(float x) {
    return 0.5f * x * (1.0f + erff(x * 0.70710678118654752f));
}

// Duplicate one f32 into both halves of an f32x2 register pair.
__device__ __forceinline__ ull dup2(float v) {
    ull r; unsigned u = __float_as_uint(v);
    asm("mov.b64 %0, {%1, %1};" : "=l"(r) : "r"(u));
    return r;
}
// Packed 2-wide fp32 FMA (Blackwell FFMA2 — only reachable via PTX f32x2).
__device__ __forceinline__ ull fma2(ull a, ull b, ull c) {
    ull d;
    asm("fma.rn.f32x2 %0, %1, %2, %3;" : "=l"(d) : "l"(a), "l"(b), "l"(c));
    return d;
}
__device__ __forceinline__ float2 unpk(ull v) {
    unsigned lo, hi;
    asm("mov.b64 {%0, %1}, %2;" : "=r"(lo), "=r"(hi) : "l"(v));
    float2 f; f.x = __uint_as_float(lo); f.y = __uint_as_float(hi);
    return f;
}

// ---------------------------------------------------------------------------
// K1: tiny MLP chain x -> 64 -> 64 -> 64, store gelu(h2). One 64-thread block
// per lc row. Also resets the owner map + counter (2 owner slots per block).
// ---------------------------------------------------------------------------
__global__ void k_mlp(const float* __restrict__ lc,
                      const float* __restrict__ W0, const float* __restrict__ b0,
                      const float* __restrict__ W1, const float* __restrict__ b1,
                      const float* __restrict__ W2, const float* __restrict__ b2) {
    __shared__ float g[IDIM];
    const int j = blockIdx.x;
    const int t = threadIdx.x;

    // owner-map reset folded in: NPOS == 2 * NLC
    if (t < 2) d_owner[2 * j + t] = -1;
    if (j == 0 && t == 0) d_cnt = 0;

    const float x = lc[j];                       // lc_values[j, 0]
    g[t] = gelu_exact(fmaf(x, W0[t], b0[t]));
    __syncthreads();

    float acc = b1[t];
#pragma unroll
    for (int k = 0; k < IDIM; ++k) acc = fmaf(g[k], W1[k * IDIM + t], acc);
    __syncthreads();
    g[t] = gelu_exact(acc);
    __syncthreads();

    acc = b2[t];
#pragma unroll
    for (int k = 0; k < IDIM; ++k) acc = fmaf(g[k], W2[k * IDIM + t], acc);

    d_g2[j * IDIM + t] = gelu_exact(acc);
}

// ---------------------------------------------------------------------------
// K2: owner map — last write (largest j) wins, matching the sequential
// (XLA-CPU) scatter's last-update-wins semantics for duplicate indices.
// Must run AFTER k_mlp: the owner-map reset is distributed across k_mlp's
// blocks, so folding this atomicMax into k_mlp would race with resets.
// ---------------------------------------------------------------------------
__global__ void k_owner(const int* __restrict__ pos_b, const int* __restrict__ pos_s) {
    int j = blockIdx.x * blockDim.x + threadIdx.x;
    if (j >= NLC) return;
    int p = pos_b[j] * SS + pos_s[j];
    atomicMax(&d_owner[p], j);
}

// ---------------------------------------------------------------------------
// K3: compact unique owned positions into a dense list (order is arbitrary
// but the per-position result is unique, so output is deterministic).
// ---------------------------------------------------------------------------
__global__ void k_compact() {
    int p = blockIdx.x * blockDim.x + threadIdx.x;
    if (p >= NPOS) return;
    int j = d_owner[p];
    if (j >= 0) {
        int i = atomicAdd(&d_cnt, 1);
        d_cpos[i] = p;
        d_cj[i]   = j;
    }
}

// ---------------------------------------------------------------------------
// K4 (fused tail): blocks [0, GEMM_BLOCKS) do the lc GEMM into owned output
// rows; blocks [GEMM_BLOCKS, +COPY_BLOCKS) do the embedding gather for
// non-owned rows. Compute-bound GEMM overlaps HBM-bound copy on-chip.
//
// GEMM tile: 64 rows x 128 cols per 256-thread block; each thread 8 rows x
// 4 cols. g staged TRANSPOSED in smem so an LDS.64 yields a row-pair
// (g_r0, g_r1) as a warp-broadcast (no bank conflicts); inner loop uses
// packed fma.rn.f32x2 (16 fma-pipe ops/k instead of 32).
// ---------------------------------------------------------------------------
__global__ __launch_bounds__(256) void k_tail(const float* __restrict__ Wout,
                                              const float* __restrict__ bout,
                                              const int* __restrict__ input_ids,
                                              const float* __restrict__ wte,
                                              float* __restrict__ out) {
    if (blockIdx.x < GEMM_BLOCKS) {
        // ----- GEMM branch -----
        // __align__(16): row-pair loads below are LDS.64; a 4-mod-8 base
        // would make every one of them misaligned (HW trap).
        __shared__ __align__(16) float s_gT[IDIM][66];   // stride 66 floats = 264 B (8B multiple)
        __shared__ int s_pos[64];

        const int cnt   = d_cnt;
        const int by    = blockIdx.x >> 4;
        const int bx    = blockIdx.x & 15;
        const int rbase = by << 6;
        if (rbase >= cnt) return;

        const int tid = threadIdx.x;

        for (int i = tid; i < 64; i += 256) {
            int r = rbase + i;
            s_pos[i] = (r < cnt) ? d_cpos[r] : -1;
        }
        for (int i = tid; i < 64 * IDIM; i += 256) {
            int row = i >> 6, k = i & 63;
            int r = rbase + row;
            s_gT[k][row] = (r < cnt) ? d_g2[d_cj[r] * IDIM + k] : 0.0f;
        }
        __syncthreads();

        const int col  = (bx << 7) + ((tid & 31) << 2);
        const int rsub = (tid >> 5) << 3;

        const float4 bv = *reinterpret_cast<const float4*>(bout + col);
        // acc[p][c] holds (row 2p, row 2p+1) of column c
        ull acc[4][4];
#pragma unroll
        for (int p = 0; p < 4; ++p) {
            acc[p][0] = dup2(bv.x); acc[p][1] = dup2(bv.y);
            acc[p][2] = dup2(bv.z); acc[p][3] = dup2(bv.w);
        }

#pragma unroll 8
        for (int k = 0; k < IDIM; ++k) {
            const float4 w = *reinterpret_cast<const float4*>(Wout + (size_t)k * HH + col);
            const ull w0 = dup2(w.x), w1 = dup2(w.y), w2 = dup2(w.z), w3 = dup2(w.w);
#pragma unroll
            for (int p = 0; p < 4; ++p) {
                const ull gp = *reinterpret_cast<const ull*>(&s_gT[k][rsub + (p << 1)]);
                acc[p][0] = fma2(gp, w0, acc[p][0]);
                acc[p][1] = fma2(gp, w1, acc[p][1]);
                acc[p][2] = fma2(gp, w2, acc[p][2]);
                acc[p][3] = fma2(gp, w3, acc[p][3]);
            }
        }

#pragma unroll
        for (int p = 0; p < 4; ++p) {
            const float2 c0 = unpk(acc[p][0]), c1 = unpk(acc[p][1]);
            const float2 c2 = unpk(acc[p][2]), c3 = unpk(acc[p][3]);
            const int r0 = s_pos[rsub + (p << 1)];
            const int r1 = s_pos[rsub + (p << 1) + 1];
            if (r0 >= 0) {
                float4 o = {c0.x, c1.x, c2.x, c3.x};
                *reinterpret_cast<float4*>(out + (size_t)r0 * HH + col) = o;
            }
            if (r1 >= 0) {
                float4 o = {c0.y, c1.y, c2.y, c3.y};
                *reinterpret_cast<float4*>(out + (size_t)r1 * HH + col) = o;
            }
        }
    } else {
        // ----- copy branch: embedding gather for non-owned rows -----
        // p is warp-uniform (16 warps per output row): owner check and id
        // load are broadcast sectors; early-return is non-divergent.
        // Streaming hints keep the touch-once wte/out streams from evicting
        // the L2-resident Wout / d_g2 / d_owner reused by GEMM blocks.
        const int idx = (blockIdx.x - GEMM_BLOCKS) * 256 + threadIdx.x;  // [0, NPOS*H4)
        const int p = idx >> 9;            // / 512 float4 per row
        if (d_owner[p] >= 0) return;
        const int c = idx & 511;
        int id = input_ids[p];
        id = max(0, min(id, VV - 1));
        const float4 v = __ldcs(reinterpret_cast<const float4*>(wte) + (size_t)id * H4 + c);
        __stcs(reinterpret_cast<float4*>(out) + idx, v);
    }
}

// ---------------------------------------------------------------------------
extern "C" void kernel_launch(void* const* d_in, const int* in_sizes, int n_in,
                              void* d_out, int out_size) {
    const int*   input_ids = (const int*)d_in[0];
    const float* lc        = (const float*)d_in[1];
    const int*   pos_b     = (const int*)d_in[2];
    const int*   pos_s     = (const int*)d_in[3];
    const float* wte       = (const float*)d_in[4];
    const float* W0        = (const float*)d_in[5];
    const float* b0        = (const float*)d_in[6];
    const float* W1        = (const float*)d_in[7];
    const float* b1        = (const float*)d_in[8];
    const float* W2        = (const float*)d_in[9];
    const float* b2        = (const float*)d_in[10];
    const float* Wout      = (const float*)d_in[11];
    const float* bout      = (const float*)d_in[12];
    float* out = (float*)d_out;

    k_mlp<<<NLC, IDIM>>>(lc, W0, b0, W1, b1, W2, b2);
    k_owner<<<(NLC + 255) / 256, 256>>>(pos_b, pos_s);
    k_compact<<<(NPOS + 255) / 256, 256>>>();
    k_tail<<<GEMM_BLOCKS + COPY_BLOCKS, 256>>>(Wout, bout, input_ids, wte, out);
}

// round 13
// speedup vs baseline: 1.4425x; 1.4425x over previous
#include <cuda_runtime.h>
#include <cuda_bf16.h>
#include <math.h>

// Problem constants
#define BB   4
#define SS   4096
#define HH   2048
#define VV   32000
#define IDIM 64
#define NLC  8192
#define NPOS (BB * SS)          // 16384 output rows
#define H4   (HH / 4)           // 512 float4 per row

#define GEMM_BLOCKS 2048                  // 16 col-tiles x 128 row-tiles
#define COPY_BLOCKS 8192                  // 2 rows per block, 4 float4/thread
#define TAIL_BLOCKS (GEMM_BLOCKS + COPY_BLOCKS)   // 10240, interleaved 1:4

typedef unsigned long long ull;

// Device scratch (no allocations allowed)
__device__ float d_g2[NLC * IDIM];   // gelu(h2) per lc row, 2 MB
__device__ int   d_owner[NPOS];      // winning lc index per position, -1 if none
__device__ int   d_cpos[NLC];        // compacted flat positions
__device__ int   d_cj[NLC];          // compacted lc indices
__device__ int   d_cnt;              // number of unique owned positions

__device__ __forceinline__ float gelu_exact(float x) {
    return 0.5f * x * (1.0f + erff(x * 0.70710678118654752f));
}

// Duplicate one f32 into both halves of an f32x2 register pair.
__device__ __forceinline__ ull dup2(float v) {
    ull r; unsigned u = __float_as_uint(v);
    asm("mov.b64 %0, {%1, %1};" : "=l"(r) : "r"(u));
    return r;
}
// Packed 2-wide fp32 FMA (Blackwell FFMA2).
__device__ __forceinline__ ull fma2(ull a, ull b, ull c) {
    ull d;
    asm("fma.rn.f32x2 %0, %1, %2, %3;" : "=l"(d) : "l"(a), "l"(b), "l"(c));
    return d;
}
__device__ __forceinline__ float2 unpk(ull v) {
    unsigned lo, hi;
    asm("mov.b64 {%0, %1}, %2;" : "=r"(lo), "=r"(hi) : "l"(v));
    float2 f; f.x = __uint_as_float(lo); f.y = __uint_as_float(hi);
    return f;
}

// ---------------------------------------------------------------------------
// K1: tiny MLP chain x -> 64 -> 64 -> 64, store gelu(h2). One 64-thread block
// per lc row. Also resets the owner map + counter (2 owner slots per block).
// ---------------------------------------------------------------------------
__global__ void k_mlp(const float* __restrict__ lc,
                      const float* __restrict__ W0, const float* __restrict__ b0,
                      const float* __restrict__ W1, const float* __restrict__ b1,
                      const float* __restrict__ W2, const float* __restrict__ b2) {
    __shared__ float g[IDIM];
    const int j = blockIdx.x;
    const int t = threadIdx.x;

    // owner-map reset folded in: NPOS == 2 * NLC
    if (t < 2) d_owner[2 * j + t] = -1;
    if (j == 0 && t == 0) d_cnt = 0;

    const float x = lc[j];                       // lc_values[j, 0]
    g[t] = gelu_exact(fmaf(x, W0[t], b0[t]));
    __syncthreads();

    float acc = b1[t];
#pragma unroll
    for (int k = 0; k < IDIM; ++k) acc = fmaf(g[k], W1[k * IDIM + t], acc);
    __syncthreads();
    g[t] = gelu_exact(acc);
    __syncthreads();

    acc = b2[t];
#pragma unroll
    for (int k = 0; k < IDIM; ++k) acc = fmaf(g[k], W2[k * IDIM + t], acc);

    d_g2[j * IDIM + t] = gelu_exact(acc);
}

// ---------------------------------------------------------------------------
// K2: owner map — last write (largest j) wins (sequential-scatter semantics).
// Must run AFTER k_mlp (owner reset is distributed across k_mlp's blocks).
// ---------------------------------------------------------------------------
__global__ void k_owner(const int* __restrict__ pos_b, const int* __restrict__ pos_s) {
    int j = blockIdx.x * blockDim.x + threadIdx.x;
    if (j >= NLC) return;
    int p = pos_b[j] * SS + pos_s[j];
    atomicMax(&d_owner[p], j);
}

// ---------------------------------------------------------------------------
// K3: compact unique owned positions into a dense list.
// ---------------------------------------------------------------------------
__global__ void k_compact() {
    int p = blockIdx.x * blockDim.x + threadIdx.x;
    if (p >= NPOS) return;
    int j = d_owner[p];
    if (j >= 0) {
        int i = atomicAdd(&d_cnt, 1);
        d_cpos[i] = p;
        d_cj[i]   = j;
    }
}

// ---------------------------------------------------------------------------
// K4 (fused tail): GEMM and copy blocks INTERLEAVED 1:4 across the grid so
// the compute-bound GEMM and HBM-bound copy genuinely overlap (R10 ncu showed
// low-index GEMM blocks serialized ahead of the copy).
//
// Copy: one block = 2 output rows; each thread issues 4 independent LDG.128
// (MLP=4) before storing — R10 showed MLP=1 left HBM at 13% (1.06 TB/s).
// GEMM: 64 rows x 128 cols per block, packed fma.rn.f32x2 inner loop.
// ---------------------------------------------------------------------------
__global__ __launch_bounds__(256) void k_tail(const float* __restrict__ Wout,
                                              const float* __restrict__ bout,
                                              const int* __restrict__ input_ids,
                                              const float* __restrict__ wte,
                                              float* __restrict__ out) {
    const int b = blockIdx.x;
    const int q = b / 5;                 // 1:4 interleave
    if (b - q * 5 == 0) {
        // ----- GEMM branch (gid = q in [0, GEMM_BLOCKS)) -----
        __shared__ __align__(16) float s_gT[IDIM][66];   // 264 B stride (8B multiple)
        __shared__ int s_pos[64];

        const int cnt   = d_cnt;
        const int by    = q >> 4;
        const int bx    = q & 15;
        const int rbase = by << 6;
        if (rbase >= cnt) return;

        const int tid = threadIdx.x;

        for (int i = tid; i < 64; i += 256) {
            int r = rbase + i;
            s_pos[i] = (r < cnt) ? d_cpos[r] : -1;
        }
        for (int i = tid; i < 64 * IDIM; i += 256) {
            int row = i >> 6, k = i & 63;
            int r = rbase + row;
            s_gT[k][row] = (r < cnt) ? d_g2[d_cj[r] * IDIM + k] : 0.0f;
        }
        __syncthreads();

        const int col  = (bx << 7) + ((tid & 31) << 2);
        const int rsub = (tid >> 5) << 3;

        const float4 bv = *reinterpret_cast<const float4*>(bout + col);
        ull acc[4][4];   // acc[p][c] = (row 2p, row 2p+1) of column c
#pragma unroll
        for (int p = 0; p < 4; ++p) {
            acc[p][0] = dup2(bv.x); acc[p][1] = dup2(bv.y);
            acc[p][2] = dup2(bv.z); acc[p][3] = dup2(bv.w);
        }

#pragma unroll 8
        for (int k = 0; k < IDIM; ++k) {
            const float4 w = *reinterpret_cast<const float4*>(Wout + (size_t)k * HH + col);
            const ull w0 = dup2(w.x), w1 = dup2(w.y), w2 = dup2(w.z), w3 = dup2(w.w);
#pragma unroll
            for (int p = 0; p < 4; ++p) {
                const ull gp = *reinterpret_cast<const ull*>(&s_gT[k][rsub + (p << 1)]);
                acc[p][0] = fma2(gp, w0, acc[p][0]);
                acc[p][1] = fma2(gp, w1, acc[p][1]);
                acc[p][2] = fma2(gp, w2, acc[p][2]);
                acc[p][3] = fma2(gp, w3, acc[p][3]);
            }
        }

#pragma unroll
        for (int p = 0; p < 4; ++p) {
            const float2 c0 = unpk(acc[p][0]), c1 = unpk(acc[p][1]);
            const float2 c2 = unpk(acc[p][2]), c3 = unpk(acc[p][3]);
            const int r0 = s_pos[rsub + (p << 1)];
            const int r1 = s_pos[rsub + (p << 1) + 1];
            if (r0 >= 0) {
                float4 o = {c0.x, c1.x, c2.x, c3.x};
                *reinterpret_cast<float4*>(out + (size_t)r0 * HH + col) = o;
            }
            if (r1 >= 0) {
                float4 o = {c0.y, c1.y, c2.y, c3.y};
                *reinterpret_cast<float4*>(out + (size_t)r1 * HH + col) = o;
            }
        }
    } else {
        // ----- copy branch (cid = b - q - 1 in [0, COPY_BLOCKS)) -----
        // Block covers rows r0 = 2*cid, r1 = r0+1. Thread t handles float4
        // columns {t, t+256} of each row: 4 independent LDG.128 in flight.
        const int cid = b - q - 1;
        const int r0 = cid << 1;
        const int r1 = r0 | 1;
        const int t  = threadIdx.x;

        const bool do0 = (d_owner[r0] < 0);
        const bool do1 = (d_owner[r1] < 0);
        if (!do0 && !do1) return;

        float4 v0, v1, v2, v3;
        if (do0) {
            int id0 = input_ids[r0];
            id0 = max(0, min(id0, VV - 1));
            const float4* s0 = reinterpret_cast<const float4*>(wte) + (size_t)id0 * H4;
            v0 = __ldcs(s0 + t);
            v1 = __ldcs(s0 + t + 256);
        }
        if (do1) {
            int id1 = input_ids[r1];
            id1 = max(0, min(id1, VV - 1));
            const float4* s1 = reinterpret_cast<const float4*>(wte) + (size_t)id1 * H4;
            v2 = __ldcs(s1 + t);
            v3 = __ldcs(s1 + t + 256);
        }

        float4* d0 = reinterpret_cast<float4*>(out) + (size_t)r0 * H4;
        float4* d1 = reinterpret_cast<float4*>(out) + (size_t)r1 * H4;
        if (do0) {
            __stcs(d0 + t,       v0);
            __stcs(d0 + t + 256, v1);
        }
        if (do1) {
            __stcs(d1 + t,       v2);
            __stcs(d1 + t + 256, v3);
        }
    }
}

// ---------------------------------------------------------------------------
extern "C" void kernel_launch(void* const* d_in, const int* in_sizes, int n_in,
                              void* d_out, int out_size) {
    const int*   input_ids = (const int*)d_in[0];
    const float* lc        = (const float*)d_in[1];
    const int*   pos_b     = (const int*)d_in[2];
    const int*   pos_s     = (const int*)d_in[3];
    const float* wte       = (const float*)d_in[4];
    const float* W0        = (const float*)d_in[5];
    const float* b0        = (const float*)d_in[6];
    const float* W1        = (const float*)d_in[7];
    const float* b1        = (const float*)d_in[8];
    const float* W2        = (const float*)d_in[9];
    const float* b2        = (const float*)d_in[10];
    const float* Wout      = (const float*)d_in[11];
    const float* bout      = (const float*)d_in[12];
    float* out = (float*)d_out;

    k_mlp<<<NLC, IDIM>>>(lc, W0, b0, W1, b1, W2, b2);
    k_owner<<<(NLC + 255) / 256, 256>>>(pos_b, pos_s);
    k_compact<<<(NPOS + 255) / 256, 256>>>();
    k_tail<<<TAIL_BLOCKS, 256>>>(Wout, bout, input_ids, wte, out);
}

// round 16
// speedup vs baseline: 1.6631x; 1.1529x over previous
#include <cuda_runtime.h>
#include <cuda_bf16.h>
#include <math.h>

// Problem constants
#define BB   4
#define SS   4096
#define HH   2048
#define VV   32000
#define IDIM 64
#define NLC  8192
#define NPOS (BB * SS)          // 16384 output rows
#define H4   (HH / 4)           // 512 float4 per row

#define GEMM_BLOCKS 4096                  // 16 col-tiles x 256 row-tiles (32 rows each)
#define COPY_BLOCKS 8192                  // 2 rows per block, 4 float4/thread
#define TAIL_BLOCKS (GEMM_BLOCKS + COPY_BLOCKS)   // 12288, interleaved 1:2

typedef unsigned long long ull;

// Device scratch (no allocations allowed)
__device__ float d_g2[NLC * IDIM];   // gelu(h2) per lc row, 2 MB
__device__ int   d_owner[NPOS];      // winning lc index per position, -1 if none
__device__ int   d_cpos[NLC];        // compacted flat positions
__device__ int   d_cj[NLC];          // compacted lc indices
__device__ int   d_cnt;              // number of unique owned positions

__device__ __forceinline__ float gelu_exact(float x) {
    return 0.5f * x * (1.0f + erff(x * 0.70710678118654752f));
}

// Duplicate one f32 into both halves of an f32x2 register pair.
__device__ __forceinline__ ull dup2(float v) {
    ull r; unsigned u = __float_as_uint(v);
    asm("mov.b64 %0, {%1, %1};" : "=l"(r) : "r"(u));
    return r;
}
// Packed 2-wide fp32 FMA (Blackwell FFMA2).
__device__ __forceinline__ ull fma2(ull a, ull b, ull c) {
    ull d;
    asm("fma.rn.f32x2 %0, %1, %2, %3;" : "=l"(d) : "l"(a), "l"(b), "l"(c));
    return d;
}
__device__ __forceinline__ float2 unpk(ull v) {
    unsigned lo, hi;
    asm("mov.b64 {%0, %1}, %2;" : "=r"(lo), "=r"(hi) : "l"(v));
    float2 f; f.x = __uint_as_float(lo); f.y = __uint_as_float(hi);
    return f;
}

// ---------------------------------------------------------------------------
// K1: tiny MLP chain x -> 64 -> 64 -> 64, store gelu(h2). One 64-thread block
// per lc row. Also resets the owner map + counter (2 owner slots per block).
// ---------------------------------------------------------------------------
__global__ void k_mlp(const float* __restrict__ lc,
                      const float* __restrict__ W0, const float* __restrict__ b0,
                      const float* __restrict__ W1, const float* __restrict__ b1,
                      const float* __restrict__ W2, const float* __restrict__ b2) {
    __shared__ float g[IDIM];
    const int j = blockIdx.x;
    const int t = threadIdx.x;

    // owner-map reset folded in: NPOS == 2 * NLC
    if (t < 2) d_owner[2 * j + t] = -1;
    if (j == 0 && t == 0) d_cnt = 0;

    const float x = lc[j];                       // lc_values[j, 0]
    g[t] = gelu_exact(fmaf(x, W0[t], b0[t]));
    __syncthreads();

    float acc = b1[t];
#pragma unroll
    for (int k = 0; k < IDIM; ++k) acc = fmaf(g[k], W1[k * IDIM + t], acc);
    __syncthreads();
    g[t] = gelu_exact(acc);
    __syncthreads();

    acc = b2[t];
#pragma unroll
    for (int k = 0; k < IDIM; ++k) acc = fmaf(g[k], W2[k * IDIM + t], acc);

    d_g2[j * IDIM + t] = gelu_exact(acc);
}

// ---------------------------------------------------------------------------
// K2: owner map — last write (largest j) wins (sequential-scatter semantics).
// Must run AFTER k_mlp (owner reset is distributed across k_mlp's blocks).
// ---------------------------------------------------------------------------
__global__ void k_owner(const int* __restrict__ pos_b, const int* __restrict__ pos_s) {
    int j = blockIdx.x * blockDim.x + threadIdx.x;
    if (j >= NLC) return;
    int p = pos_b[j] * SS + pos_s[j];
    atomicMax(&d_owner[p], j);
}

// ---------------------------------------------------------------------------
// K3: compact unique owned positions into a dense list.
// ---------------------------------------------------------------------------
__global__ void k_compact() {
    int p = blockIdx.x * blockDim.x + threadIdx.x;
    if (p >= NPOS) return;
    int j = d_owner[p];
    if (j >= 0) {
        int i = atomicAdd(&d_cnt, 1);
        d_cpos[i] = p;
        d_cj[i]   = j;
    }
}

// ---------------------------------------------------------------------------
// K4 (fused tail), R14: register diet for occupancy.
// R13 ncu: occ=35.2% == 3-blocks/SM reg cap (68 regs); DRAM 21%, fma 25%,
// issue 25% — concurrency-starved on both sides. Fix: GEMM tile shrunk to
// 32 rows x 128 cols (8 ull accs/thread = 16 regs), __launch_bounds__(256,6)
// forces <=42 regs -> 6 blocks/SM. Interleave 1:2 so ~2 GEMM blocks/SM
// (16 warps, enough to saturate fma pipe) + ~4 copy blocks/SM (65 KB
// outstanding LDG.128 per SM -> DRAM-bound copy).
// ---------------------------------------------------------------------------
__global__ __launch_bounds__(256, 6) void k_tail(const float* __restrict__ Wout,
                                                 const float* __restrict__ bout,
                                                 const int* __restrict__ input_ids,
                                                 const float* __restrict__ wte,
                                                 float* __restrict__ out) {
    const int b = blockIdx.x;
    const int q = b / 3;                 // 1:2 interleave (b%3==0 -> GEMM)
    if (b - q * 3 == 0) {
        // ----- GEMM branch (gid = q in [0, GEMM_BLOCKS)) -----
        // 32 rows x 128 cols per block. s_gT transposed; stride 34 floats
        // = 136 B (8B multiple); __align__(16) keeps LDS.64 legal.
        __shared__ __align__(16) float s_gT[IDIM][34];
        __shared__ int s_pos[32];

        const int cnt   = d_cnt;
        const int by    = q >> 4;        // [0, 256) row tiles
        const int bx    = q & 15;        // [0, 16) col tiles
        const int rbase = by << 5;       // 32 rows per tile
        if (rbase >= cnt) return;

        const int tid = threadIdx.x;

        if (tid < 32) {
            int r = rbase + tid;
            s_pos[tid] = (r < cnt) ? d_cpos[r] : -1;
        }
        for (int i = tid; i < 32 * IDIM; i += 256) {
            int row = i >> 6, k = i & 63;
            int r = rbase + row;
            s_gT[k][row] = (r < cnt) ? d_g2[d_cj[r] * IDIM + k] : 0.0f;
        }
        __syncthreads();

        const int col  = (bx << 7) + ((tid & 31) << 2);
        const int rsub = (tid >> 5) << 2;   // 8 warps x 4 rows

        const float4 bv = *reinterpret_cast<const float4*>(bout + col);
        ull acc[2][4];   // acc[p][c] = (row 2p, row 2p+1) of column c
#pragma unroll
        for (int p = 0; p < 2; ++p) {
            acc[p][0] = dup2(bv.x); acc[p][1] = dup2(bv.y);
            acc[p][2] = dup2(bv.z); acc[p][3] = dup2(bv.w);
        }

#pragma unroll 8
        for (int k = 0; k < IDIM; ++k) {
            const float4 w = *reinterpret_cast<const float4*>(Wout + (size_t)k * HH + col);
            const ull w0 = dup2(w.x), w1 = dup2(w.y), w2 = dup2(w.z), w3 = dup2(w.w);
#pragma unroll
            for (int p = 0; p < 2; ++p) {
                const ull gp = *reinterpret_cast<const ull*>(&s_gT[k][rsub + (p << 1)]);
                acc[p][0] = fma2(gp, w0, acc[p][0]);
                acc[p][1] = fma2(gp, w1, acc[p][1]);
                acc[p][2] = fma2(gp, w2, acc[p][2]);
                acc[p][3] = fma2(gp, w3, acc[p][3]);
            }
        }

#pragma unroll
        for (int p = 0; p < 2; ++p) {
            const float2 c0 = unpk(acc[p][0]), c1 = unpk(acc[p][1]);
            const float2 c2 = unpk(acc[p][2]), c3 = unpk(acc[p][3]);
            const int r0 = s_pos[rsub + (p << 1)];
            const int r1 = s_pos[rsub + (p << 1) + 1];
            if (r0 >= 0) {
                float4 o = {c0.x, c1.x, c2.x, c3.x};
                *reinterpret_cast<float4*>(out + (size_t)r0 * HH + col) = o;
            }
            if (r1 >= 0) {
                float4 o = {c0.y, c1.y, c2.y, c3.y};
                *reinterpret_cast<float4*>(out + (size_t)r1 * HH + col) = o;
            }
        }
    } else {
        // ----- copy branch (cid = b - q - 1 in [0, COPY_BLOCKS)) -----
        // Block covers rows r0 = 2*cid, r1 = r0+1. Thread t handles float4
        // columns {t, t+256} of each row: 4 independent LDG.128 in flight.
        const int cid = b - q - 1;
        const int r0 = cid << 1;
        const int r1 = r0 | 1;
        const int t  = threadIdx.x;

        const bool do0 = (d_owner[r0] < 0);
        const bool do1 = (d_owner[r1] < 0);
        if (!do0 && !do1) return;

        float4 v0, v1, v2, v3;
        if (do0) {
            int id0 = input_ids[r0];
            id0 = max(0, min(id0, VV - 1));
            const float4* s0 = reinterpret_cast<const float4*>(wte) + (size_t)id0 * H4;
            v0 = __ldcs(s0 + t);
            v1 = __ldcs(s0 + t + 256);
        }
        if (do1) {
            int id1 = input_ids[r1];
            id1 = max(0, min(id1, VV - 1));
            const float4* s1 = reinterpret_cast<const float4*>(wte) + (size_t)id1 * H4;
            v2 = __ldcs(s1 + t);
            v3 = __ldcs(s1 + t + 256);
        }

        float4* d0 = reinterpret_cast<float4*>(out) + (size_t)r0 * H4;
        float4* d1 = reinterpret_cast<float4*>(out) + (size_t)r1 * H4;
        if (do0) {
            __stcs(d0 + t,       v0);
            __stcs(d0 + t + 256, v1);
        }
        if (do1) {
            __stcs(d1 + t,       v2);
            __stcs(d1 + t + 256, v3);
        }
    }
}

// ---------------------------------------------------------------------------
extern "C" void kernel_launch(void* const* d_in, const int* in_sizes, int n_in,
                              void* d_out, int out_size) {
    const int*   input_ids = (const int*)d_in[0];
    const float* lc        = (const float*)d_in[1];
    const int*   pos_b     = (const int*)d_in[2];
    const int*   pos_s     = (const int*)d_in[3];
    const float* wte       = (const float*)d_in[4];
    const float* W0        = (const float*)d_in[5];
    const float* b0        = (const float*)d_in[6];
    const float* W1        = (const float*)d_in[7];
    const float* b1        = (const float*)d_in[8];
    const float* W2        = (const float*)d_in[9];
    const float* b2        = (const float*)d_in[10];
    const float* Wout      = (const float*)d_in[11];
    const float* bout      = (const float*)d_in[12];
    float* out = (float*)d_out;

    k_mlp<<<NLC, IDIM>>>(lc, W0, b0, W1, b1, W2, b2);
    k_owner<<<(NLC + 255) / 256, 256>>>(pos_b, pos_s);
    k_compact<<<(NPOS + 255) / 256, 256>>>();
    k_tail<<<TAIL_BLOCKS, 256>>>(Wout, bout, input_ids, wte, out);
}